// round 11
// baseline (speedup 1.0000x reference)
#include <cuda_runtime.h>
#include <cuda_bf16.h>

// ---------------------------------------------------------------------------
// GCNRegression: 2x GCNConv(+relu) + linear head.
// N=100000, E=1.6M, F=128, H=64. edge_index arrives int32.
//
// R10: GEMM rebuilt as 4x4 register-tiled (64x64 block tile, K chunked by 64).
//      Per k4-step: 8 LDS.128 feed 64 FMAs (was 8 LDS per 16 FMAs) -> FFMA
//      becomes the binding pipe instead of L1 (ncu R9: L1=84.5%, fma=27.3%).
//      Everything else identical to R9 (best known).
//
// Order: zero(1) hist(2) scan1(3) gemm128(4) scan2(5) scan3(6) scatter(7)
//        agg_relu(8) gemm64(9) agg_head(10)
// ---------------------------------------------------------------------------

#define NMAX 100000
#define EMAX 1600000
#define HID 64
#define SCAN_CHUNK 4096

__device__ __align__(16) float2 g_dc[NMAX];            // {deg_sum, count}
__device__ __align__(16) float  g_dis[NMAX];
__device__ __align__(16) int    g_rowptr[NMAX + 1];
__device__ __align__(16) int    g_pos[NMAX];
__device__ __align__(16) int    g_bsum[1024];
__device__ __align__(16) int    g_boff[1024];
__device__ __align__(16) float2 g_edge[EMAX];          // {src_as_float_bits, coef}
__device__ __align__(16) float  g_bufA[(size_t)NMAX * HID];
__device__ __align__(16) float  g_bufB[(size_t)NMAX * HID];

// ---- zero {deg, cnt} -------------------------------------------------------
__global__ void k_zero_dc(int n) {
    int i = blockIdx.x * blockDim.x + threadIdx.x;
    if (i < n) g_dc[i] = make_float2(0.f, 0.f);
}

// ---- weighted in-degree + histogram, one vector RED per edge ---------------
__global__ void k_deg_hist(const int* __restrict__ dst,
                           const float* __restrict__ ew, int E) {
    int e = blockIdx.x * blockDim.x + threadIdx.x;
    if (e < E) {
        int d = dst[e];
        float w = ew[e];
        asm volatile("red.global.add.v2.f32 [%0], {%1,%2};"
                     :: "l"(&g_dc[d]), "f"(w), "f"(1.0f) : "memory");
    }
}

// ---- scan phase 1 over counts (+ fused dis = rsqrt(1+deg)) -----------------
__global__ void k_scan1(int n) {
    __shared__ int ts[1024];
    int t = threadIdx.x, b = blockIdx.x;
    int base = b * SCAN_CHUNK + t * 4;
    int c[4];
#pragma unroll
    for (int r = 0; r < 4; r++) {
        if (base + r < n) {
            float2 dc = g_dc[base + r];
            c[r] = (int)dc.y;
            g_dis[base + r] = rsqrtf(1.0f + dc.x);
        } else c[r] = 0;
    }
    int s = c[0] + c[1] + c[2] + c[3];
    ts[t] = s;
    __syncthreads();
    for (int d = 1; d < 1024; d <<= 1) {
        int v = (t >= d) ? ts[t - d] : 0;
        __syncthreads();
        ts[t] += v;
        __syncthreads();
    }
    int excl = ts[t] - s;
    if (base + 0 < n) g_rowptr[base + 0] = excl;
    if (base + 1 < n) g_rowptr[base + 1] = excl + c[0];
    if (base + 2 < n) g_rowptr[base + 2] = excl + c[0] + c[1];
    if (base + 3 < n) g_rowptr[base + 3] = excl + c[0] + c[1] + c[2];
    if (t == 1023) g_bsum[b] = ts[1023];
}

// ---- scan phase 2: scan block sums (nb <= 1024) ----------------------------
__global__ void k_scan2(int nb, int n, int E) {
    __shared__ int ts[1024];
    int t = threadIdx.x;
    int v = (t < nb) ? g_bsum[t] : 0;
    ts[t] = v;
    __syncthreads();
    for (int d = 1; d < 1024; d <<= 1) {
        int u = (t >= d) ? ts[t - d] : 0;
        __syncthreads();
        ts[t] += u;
        __syncthreads();
    }
    if (t < nb) g_boff[t] = ts[t] - v;
    if (t == 0) g_rowptr[n] = E;
}

// ---- scan phase 3: add block offsets, init cursors -------------------------
__global__ void k_scan3(int n) {
    int i = blockIdx.x * blockDim.x + threadIdx.x;
    if (i < n) {
        int r = g_rowptr[i] + g_boff[i / SCAN_CHUNK];
        g_rowptr[i] = r;
        g_pos[i] = r;
    }
}

// ---- scatter edges into dst-sorted CSR order (packed meta) -----------------
__global__ void k_scatter(const int* __restrict__ src,
                          const int* __restrict__ dst,
                          const float* __restrict__ ew, int E) {
    int e = blockIdx.x * blockDim.x + threadIdx.x;
    if (e >= E) return;
    int s = src[e];
    int d = dst[e];
    int p = atomicAdd(&g_pos[d], 1);
    g_edge[p] = make_float2(__int_as_float(s), g_dis[s] * ew[e] * g_dis[d]);
}

// ---- packed helper: a += s * w (float4 lanewise) ---------------------------
__device__ __forceinline__ void fma4(float4& a, float s, const float4 w) {
    a.x = fmaf(s, w.x, a.x);
    a.y = fmaf(s, w.y, a.y);
    a.z = fmaf(s, w.z, a.z);
    a.w = fmaf(s, w.w, a.w);
}

// ---- Y[n,64] = X[n,K] @ W[64,K]^T ; 4x4 register tiling --------------------
// 256 thr = 16x16 thread grid; block tile 64 rows x 64 cols; K chunked by 64.
// Per k4-step/thread: 4 broadcast LDS.128 (x) + 4 LDS.128 (w) feed 64 FMAs.
template <int K>
__global__ __launch_bounds__(256) void k_gemm(
        const float* __restrict__ X, const float* __restrict__ W,
        float* __restrict__ Y, int n) {
    __shared__ float4 Xs4[64][16];          // 16 KB: 64 rows x 64 k (chunk)
    __shared__ float  Wt[64][HID + 4];      // 17 KB: Wt[k][c], +4 pad keeps
                                            //        &Wt[k][4*tc] 16B-aligned
    const int tid  = threadIdx.x;
    const int row0 = blockIdx.x * 64;
    const int r0   = (tid >> 4) * 4;        // thread-row * 4
    const int c0   = (tid & 15) * 4;        // thread-col * 4

    const float4* X4 = (const float4*)X;

    float4 acc0 = make_float4(0.f, 0.f, 0.f, 0.f);
    float4 acc1 = acc0, acc2 = acc0, acc3 = acc0;

    for (int kc = 0; kc < K; kc += 64) {
        if (kc) __syncthreads();
        // stage X chunk: 64 rows x 16 float4, coalesced
#pragma unroll
        for (int i = 0; i < 4; i++) {
            int idx = tid + i * 256;
            int r = idx >> 4, q = idx & 15;
            int row = row0 + r;
            Xs4[r][q] = (row < n) ? X4[(size_t)row * (K / 4) + (kc >> 2) + q]
                                  : make_float4(0.f, 0.f, 0.f, 0.f);
        }
        // stage W chunk transposed: Wt[k][c] = W[c*K + kc + k] (coalesced in k)
#pragma unroll
        for (int i = 0; i < 16; i++) {
            int idx = tid + i * 256;
            int c = idx >> 6, k = idx & 63;
            Wt[k][c] = W[(size_t)c * K + kc + k];
        }
        __syncthreads();

#pragma unroll
        for (int t = 0; t < 16; t++) {
            float4 x0 = Xs4[r0 + 0][t];
            float4 x1 = Xs4[r0 + 1][t];
            float4 x2 = Xs4[r0 + 2][t];
            float4 x3 = Xs4[r0 + 3][t];
            float4 w0 = *(const float4*)&Wt[4 * t + 0][c0];
            float4 w1 = *(const float4*)&Wt[4 * t + 1][c0];
            float4 w2 = *(const float4*)&Wt[4 * t + 2][c0];
            float4 w3 = *(const float4*)&Wt[4 * t + 3][c0];
            fma4(acc0, x0.x, w0); fma4(acc0, x0.y, w1); fma4(acc0, x0.z, w2); fma4(acc0, x0.w, w3);
            fma4(acc1, x1.x, w0); fma4(acc1, x1.y, w1); fma4(acc1, x1.z, w2); fma4(acc1, x1.w, w3);
            fma4(acc2, x2.x, w0); fma4(acc2, x2.y, w1); fma4(acc2, x2.z, w2); fma4(acc2, x2.w, w3);
            fma4(acc3, x3.x, w0); fma4(acc3, x3.y, w1); fma4(acc3, x3.z, w2); fma4(acc3, x3.w, w3);
        }
    }

    const int tc = tid & 15;
#pragma unroll
    for (int i = 0; i < 4; i++) {
        int row = row0 + r0 + i;
        if (row < n) {
            float4 a = (i == 0) ? acc0 : (i == 1) ? acc1 : (i == 2) ? acc2 : acc3;
            ((float4*)(Y + (size_t)row * HID))[tc] = a;
        }
    }
}

// ---- segmented-sum body: acc (float2/lane) over a node's edge list ---------
__device__ __forceinline__ void agg_body(const float* __restrict__ xw,
                                         int node, int lane,
                                         float& ax, float& ay) {
    int j   = g_rowptr[node];
    int end = g_rowptr[node + 1];
    for (; j + 3 < end; j += 4) {
        float2 m0 = g_edge[j],     m1 = g_edge[j + 1];
        float2 m2 = g_edge[j + 2], m3 = g_edge[j + 3];
        int s0 = __float_as_int(m0.x), s1 = __float_as_int(m1.x);
        int s2 = __float_as_int(m2.x), s3 = __float_as_int(m3.x);
        float2 v0 = __ldg((const float2*)(xw + (size_t)s0 * HID) + lane);
        float2 v1 = __ldg((const float2*)(xw + (size_t)s1 * HID) + lane);
        float2 v2 = __ldg((const float2*)(xw + (size_t)s2 * HID) + lane);
        float2 v3 = __ldg((const float2*)(xw + (size_t)s3 * HID) + lane);
        ax = fmaf(m0.y, v0.x, ax); ay = fmaf(m0.y, v0.y, ay);
        ax = fmaf(m1.y, v1.x, ax); ay = fmaf(m1.y, v1.y, ay);
        ax = fmaf(m2.y, v2.x, ax); ay = fmaf(m2.y, v2.y, ay);
        ax = fmaf(m3.y, v3.x, ax); ay = fmaf(m3.y, v3.y, ay);
    }
    for (; j < end; j++) {
        float2 m = g_edge[j];
        int s = __float_as_int(m.x);
        float2 v = __ldg((const float2*)(xw + (size_t)s * HID) + lane);
        ax = fmaf(m.y, v.x, ax); ay = fmaf(m.y, v.y, ay);
    }
}

// ---- layer aggregation + self-loop + bias + relu (1 warp/node) -------------
__global__ void k_agg_relu(const float* __restrict__ xw,
                           const float* __restrict__ b,
                           float* __restrict__ out, int n) {
    int node = (blockIdx.x * blockDim.x + threadIdx.x) >> 5;
    int lane = threadIdx.x & 31;
    if (node >= n) return;
    float ax = 0.f, ay = 0.f;
    agg_body(xw, node, lane, ax, ay);
    float ds = g_dis[node];
    float d2 = ds * ds;
    float2 xv = __ldg((const float2*)(xw + (size_t)node * HID) + lane);
    float2 bb = __ldg((const float2*)b + lane);
    float2 r;
    r.x = fmaxf(fmaf(d2, xv.x, ax) + bb.x, 0.f);
    r.y = fmaxf(fmaf(d2, xv.y, ay) + bb.y, 0.f);
    ((float2*)(out + (size_t)node * HID))[lane] = r;
}

// ---- final aggregation + relu + head dot W3 (1 warp/node) ------------------
__global__ void k_agg_head(const float* __restrict__ xw,
                           const float* __restrict__ b2,
                           const float* __restrict__ W3,
                           const float* __restrict__ b3,
                           float* __restrict__ out, int n) {
    int node = (blockIdx.x * blockDim.x + threadIdx.x) >> 5;
    int lane = threadIdx.x & 31;
    if (node >= n) return;
    float ax = 0.f, ay = 0.f;
    agg_body(xw, node, lane, ax, ay);
    float ds = g_dis[node];
    float d2 = ds * ds;
    float2 xv = __ldg((const float2*)(xw + (size_t)node * HID) + lane);
    float2 bb = __ldg((const float2*)b2 + lane);
    float h0 = fmaxf(fmaf(d2, xv.x, ax) + bb.x, 0.f);
    float h1 = fmaxf(fmaf(d2, xv.y, ay) + bb.y, 0.f);
    float2 w = __ldg((const float2*)W3 + lane);
    float sum = fmaf(h0, w.x, h1 * w.y);
#pragma unroll
    for (int off = 16; off; off >>= 1)
        sum += __shfl_xor_sync(0xffffffffu, sum, off);
    if (lane == 0) out[node] = sum + b3[0];
}

extern "C" void kernel_launch(void* const* d_in, const int* in_sizes, int n_in,
                              void* d_out, int out_size) {
    const float* x   = (const float*)d_in[0];
    const int*   ei  = (const int*)d_in[1];       // int32 (JAX x64 disabled)
    const float* ew  = (const float*)d_in[2];
    // d_in[3] = batch (unused)
    const float* W1  = (const float*)d_in[4];
    const float* b1  = (const float*)d_in[5];
    const float* W2  = (const float*)d_in[6];
    const float* b2  = (const float*)d_in[7];
    const float* W3  = (const float*)d_in[8];
    const float* b3  = (const float*)d_in[9];
    float*       out = (float*)d_out;

    const int n = in_sizes[0] / 128;   // 100000
    const int E = in_sizes[1] / 2;     // 1600000
    const int* src = ei;
    const int* dst = ei + E;

    float *dA, *dB;
    cudaGetSymbolAddress((void**)&dA, g_bufA);
    cudaGetSymbolAddress((void**)&dB, g_bufB);

    const int TB = 256;
    const int NB = (n + SCAN_CHUNK - 1) / SCAN_CHUNK;
    const int GB = (n + 63) / 64;                 // gemm blocks (64 rows each)

    // single stream; gemm128 4th (ncu profiles launch #4)
    k_zero_dc<<<(n + TB - 1) / TB, TB>>>(n);                      // 1
    k_deg_hist<<<(E + TB - 1) / TB, TB>>>(dst, ew, E);            // 2
    k_scan1<<<NB, 1024>>>(n);                                     // 3
    k_gemm<128><<<GB, TB>>>(x, W1, dA, n);                        // 4  <- profiled
    k_scan2<<<1, 1024>>>(NB, n, E);                               // 5
    k_scan3<<<(n + TB - 1) / TB, TB>>>(n);                        // 6
    k_scatter<<<(E + TB - 1) / TB, TB>>>(src, dst, ew, E);        // 7
    k_agg_relu<<<(n * 32 + TB - 1) / TB, TB>>>(dA, b1, dB, n);    // 8
    k_gemm<64><<<GB, TB>>>(dB, W2, dA, n);                        // 9
    k_agg_head<<<(n * 32 + TB - 1) / TB, TB>>>(dA, b2, W3, b3, out, n); // 10
}

// round 13
// speedup vs baseline: 1.0374x; 1.0374x over previous
#include <cuda_runtime.h>
#include <cuda_bf16.h>

// ---------------------------------------------------------------------------
// GCNRegression: 2x GCNConv(+relu) + linear head.
// N=100000, E=1.6M, F=128, H=64. edge_index arrives int32.
//
// R13 == R12 resubmitted (R12 hit a broker/container infra failure, never
// ran; same signature as R7, which a plain resubmit fixed).
// R12 = R10 (best, 226.6us) + ONE change: CSR build chain forked onto a
// second stream, overlapped with gemm128 (independent work, different HW
// resources: LTS atomics vs L1/FFMA). Join before agg_relu.
//
//   s0: gemm128 ----------------------\
//   s2: zero hist scan1 scan2 scan3 scatter --> join --> agg_relu gemm64 agg_head
// ---------------------------------------------------------------------------

#define NMAX 100000
#define EMAX 1600000
#define HID 64
#define SCAN_CHUNK 4096

__device__ __align__(16) float2 g_dc[NMAX];            // {deg_sum, count}
__device__ __align__(16) float  g_dis[NMAX];
__device__ __align__(16) int    g_rowptr[NMAX + 1];
__device__ __align__(16) int    g_pos[NMAX];
__device__ __align__(16) int    g_bsum[1024];
__device__ __align__(16) int    g_boff[1024];
__device__ __align__(16) float2 g_edge[EMAX];          // {src_as_float_bits, coef}
__device__ __align__(16) float  g_bufA[(size_t)NMAX * HID];
__device__ __align__(16) float  g_bufB[(size_t)NMAX * HID];

// ---- zero {deg, cnt} -------------------------------------------------------
__global__ void k_zero_dc(int n) {
    int i = blockIdx.x * blockDim.x + threadIdx.x;
    if (i < n) g_dc[i] = make_float2(0.f, 0.f);
}

// ---- weighted in-degree + histogram, one vector RED per edge ---------------
__global__ void k_deg_hist(const int* __restrict__ dst,
                           const float* __restrict__ ew, int E) {
    int e = blockIdx.x * blockDim.x + threadIdx.x;
    if (e < E) {
        int d = dst[e];
        float w = ew[e];
        asm volatile("red.global.add.v2.f32 [%0], {%1,%2};"
                     :: "l"(&g_dc[d]), "f"(w), "f"(1.0f) : "memory");
    }
}

// ---- scan phase 1 over counts (+ fused dis = rsqrt(1+deg)) -----------------
__global__ void k_scan1(int n) {
    __shared__ int ts[1024];
    int t = threadIdx.x, b = blockIdx.x;
    int base = b * SCAN_CHUNK + t * 4;
    int c[4];
#pragma unroll
    for (int r = 0; r < 4; r++) {
        if (base + r < n) {
            float2 dc = g_dc[base + r];
            c[r] = (int)dc.y;
            g_dis[base + r] = rsqrtf(1.0f + dc.x);
        } else c[r] = 0;
    }
    int s = c[0] + c[1] + c[2] + c[3];
    ts[t] = s;
    __syncthreads();
    for (int d = 1; d < 1024; d <<= 1) {
        int v = (t >= d) ? ts[t - d] : 0;
        __syncthreads();
        ts[t] += v;
        __syncthreads();
    }
    int excl = ts[t] - s;
    if (base + 0 < n) g_rowptr[base + 0] = excl;
    if (base + 1 < n) g_rowptr[base + 1] = excl + c[0];
    if (base + 2 < n) g_rowptr[base + 2] = excl + c[0] + c[1];
    if (base + 3 < n) g_rowptr[base + 3] = excl + c[0] + c[1] + c[2];
    if (t == 1023) g_bsum[b] = ts[1023];
}

// ---- scan phase 2: scan block sums (nb <= 1024) ----------------------------
__global__ void k_scan2(int nb, int n, int E) {
    __shared__ int ts[1024];
    int t = threadIdx.x;
    int v = (t < nb) ? g_bsum[t] : 0;
    ts[t] = v;
    __syncthreads();
    for (int d = 1; d < 1024; d <<= 1) {
        int u = (t >= d) ? ts[t - d] : 0;
        __syncthreads();
        ts[t] += u;
        __syncthreads();
    }
    if (t < nb) g_boff[t] = ts[t] - v;
    if (t == 0) g_rowptr[n] = E;
}

// ---- scan phase 3: add block offsets, init cursors -------------------------
__global__ void k_scan3(int n) {
    int i = blockIdx.x * blockDim.x + threadIdx.x;
    if (i < n) {
        int r = g_rowptr[i] + g_boff[i / SCAN_CHUNK];
        g_rowptr[i] = r;
        g_pos[i] = r;
    }
}

// ---- scatter edges into dst-sorted CSR order (packed meta) -----------------
__global__ void k_scatter(const int* __restrict__ src,
                          const int* __restrict__ dst,
                          const float* __restrict__ ew, int E) {
    int e = blockIdx.x * blockDim.x + threadIdx.x;
    if (e >= E) return;
    int s = src[e];
    int d = dst[e];
    int p = atomicAdd(&g_pos[d], 1);
    g_edge[p] = make_float2(__int_as_float(s), g_dis[s] * ew[e] * g_dis[d]);
}

// ---- packed helper: a += s * w (float4 lanewise) ---------------------------
__device__ __forceinline__ void fma4(float4& a, float s, const float4 w) {
    a.x = fmaf(s, w.x, a.x);
    a.y = fmaf(s, w.y, a.y);
    a.z = fmaf(s, w.z, a.z);
    a.w = fmaf(s, w.w, a.w);
}

// ---- Y[n,64] = X[n,K] @ W[64,K]^T ; 4x4 register tiling --------------------
// 256 thr = 16x16 thread grid; block tile 64 rows x 64 cols; K chunked by 64.
template <int K>
__global__ __launch_bounds__(256) void k_gemm(
        const float* __restrict__ X, const float* __restrict__ W,
        float* __restrict__ Y, int n) {
    __shared__ float4 Xs4[64][16];          // 16 KB
    __shared__ float  Wt[64][HID + 4];      // 17 KB, +4 pad keeps rows 16B-aligned
    const int tid  = threadIdx.x;
    const int row0 = blockIdx.x * 64;
    const int r0   = (tid >> 4) * 4;
    const int c0   = (tid & 15) * 4;

    const float4* X4 = (const float4*)X;

    float4 acc0 = make_float4(0.f, 0.f, 0.f, 0.f);
    float4 acc1 = acc0, acc2 = acc0, acc3 = acc0;

    for (int kc = 0; kc < K; kc += 64) {
        if (kc) __syncthreads();
#pragma unroll
        for (int i = 0; i < 4; i++) {
            int idx = tid + i * 256;
            int r = idx >> 4, q = idx & 15;
            int row = row0 + r;
            Xs4[r][q] = (row < n) ? X4[(size_t)row * (K / 4) + (kc >> 2) + q]
                                  : make_float4(0.f, 0.f, 0.f, 0.f);
        }
#pragma unroll
        for (int i = 0; i < 16; i++) {
            int idx = tid + i * 256;
            int c = idx >> 6, k = idx & 63;
            Wt[k][c] = W[(size_t)c * K + kc + k];
        }
        __syncthreads();

#pragma unroll
        for (int t = 0; t < 16; t++) {
            float4 x0 = Xs4[r0 + 0][t];
            float4 x1 = Xs4[r0 + 1][t];
            float4 x2 = Xs4[r0 + 2][t];
            float4 x3 = Xs4[r0 + 3][t];
            float4 w0 = *(const float4*)&Wt[4 * t + 0][c0];
            float4 w1 = *(const float4*)&Wt[4 * t + 1][c0];
            float4 w2 = *(const float4*)&Wt[4 * t + 2][c0];
            float4 w3 = *(const float4*)&Wt[4 * t + 3][c0];
            fma4(acc0, x0.x, w0); fma4(acc0, x0.y, w1); fma4(acc0, x0.z, w2); fma4(acc0, x0.w, w3);
            fma4(acc1, x1.x, w0); fma4(acc1, x1.y, w1); fma4(acc1, x1.z, w2); fma4(acc1, x1.w, w3);
            fma4(acc2, x2.x, w0); fma4(acc2, x2.y, w1); fma4(acc2, x2.z, w2); fma4(acc2, x2.w, w3);
            fma4(acc3, x3.x, w0); fma4(acc3, x3.y, w1); fma4(acc3, x3.z, w2); fma4(acc3, x3.w, w3);
        }
    }

    const int tc = tid & 15;
#pragma unroll
    for (int i = 0; i < 4; i++) {
        int row = row0 + r0 + i;
        if (row < n) {
            float4 a = (i == 0) ? acc0 : (i == 1) ? acc1 : (i == 2) ? acc2 : acc3;
            ((float4*)(Y + (size_t)row * HID))[tc] = a;
        }
    }
}

// ---- segmented-sum body: acc (float2/lane) over a node's edge list ---------
__device__ __forceinline__ void agg_body(const float* __restrict__ xw,
                                         int node, int lane,
                                         float& ax, float& ay) {
    int j   = g_rowptr[node];
    int end = g_rowptr[node + 1];
    for (; j + 3 < end; j += 4) {
        float2 m0 = g_edge[j],     m1 = g_edge[j + 1];
        float2 m2 = g_edge[j + 2], m3 = g_edge[j + 3];
        int s0 = __float_as_int(m0.x), s1 = __float_as_int(m1.x);
        int s2 = __float_as_int(m2.x), s3 = __float_as_int(m3.x);
        float2 v0 = __ldg((const float2*)(xw + (size_t)s0 * HID) + lane);
        float2 v1 = __ldg((const float2*)(xw + (size_t)s1 * HID) + lane);
        float2 v2 = __ldg((const float2*)(xw + (size_t)s2 * HID) + lane);
        float2 v3 = __ldg((const float2*)(xw + (size_t)s3 * HID) + lane);
        ax = fmaf(m0.y, v0.x, ax); ay = fmaf(m0.y, v0.y, ay);
        ax = fmaf(m1.y, v1.x, ax); ay = fmaf(m1.y, v1.y, ay);
        ax = fmaf(m2.y, v2.x, ax); ay = fmaf(m2.y, v2.y, ay);
        ax = fmaf(m3.y, v3.x, ax); ay = fmaf(m3.y, v3.y, ay);
    }
    for (; j < end; j++) {
        float2 m = g_edge[j];
        int s = __float_as_int(m.x);
        float2 v = __ldg((const float2*)(xw + (size_t)s * HID) + lane);
        ax = fmaf(m.y, v.x, ax); ay = fmaf(m.y, v.y, ay);
    }
}

// ---- layer aggregation + self-loop + bias + relu (1 warp/node) -------------
__global__ void k_agg_relu(const float* __restrict__ xw,
                           const float* __restrict__ b,
                           float* __restrict__ out, int n) {
    int node = (blockIdx.x * blockDim.x + threadIdx.x) >> 5;
    int lane = threadIdx.x & 31;
    if (node >= n) return;
    float ax = 0.f, ay = 0.f;
    agg_body(xw, node, lane, ax, ay);
    float ds = g_dis[node];
    float d2 = ds * ds;
    float2 xv = __ldg((const float2*)(xw + (size_t)node * HID) + lane);
    float2 bb = __ldg((const float2*)b + lane);
    float2 r;
    r.x = fmaxf(fmaf(d2, xv.x, ax) + bb.x, 0.f);
    r.y = fmaxf(fmaf(d2, xv.y, ay) + bb.y, 0.f);
    ((float2*)(out + (size_t)node * HID))[lane] = r;
}

// ---- final aggregation + relu + head dot W3 (1 warp/node) ------------------
__global__ void k_agg_head(const float* __restrict__ xw,
                           const float* __restrict__ b2,
                           const float* __restrict__ W3,
                           const float* __restrict__ b3,
                           float* __restrict__ out, int n) {
    int node = (blockIdx.x * blockDim.x + threadIdx.x) >> 5;
    int lane = threadIdx.x & 31;
    if (node >= n) return;
    float ax = 0.f, ay = 0.f;
    agg_body(xw, node, lane, ax, ay);
    float ds = g_dis[node];
    float d2 = ds * ds;
    float2 xv = __ldg((const float2*)(xw + (size_t)node * HID) + lane);
    float2 bb = __ldg((const float2*)b2 + lane);
    float h0 = fmaxf(fmaf(d2, xv.x, ax) + bb.x, 0.f);
    float h1 = fmaxf(fmaf(d2, xv.y, ay) + bb.y, 0.f);
    float2 w = __ldg((const float2*)W3 + lane);
    float sum = fmaf(h0, w.x, h1 * w.y);
#pragma unroll
    for (int off = 16; off; off >>= 1)
        sum += __shfl_xor_sync(0xffffffffu, sum, off);
    if (lane == 0) out[node] = sum + b3[0];
}

extern "C" void kernel_launch(void* const* d_in, const int* in_sizes, int n_in,
                              void* d_out, int out_size) {
    const float* x   = (const float*)d_in[0];
    const int*   ei  = (const int*)d_in[1];       // int32 (JAX x64 disabled)
    const float* ew  = (const float*)d_in[2];
    // d_in[3] = batch (unused)
    const float* W1  = (const float*)d_in[4];
    const float* b1  = (const float*)d_in[5];
    const float* W2  = (const float*)d_in[6];
    const float* b2  = (const float*)d_in[7];
    const float* W3  = (const float*)d_in[8];
    const float* b3  = (const float*)d_in[9];
    float*       out = (float*)d_out;

    const int n = in_sizes[0] / 128;   // 100000
    const int E = in_sizes[1] / 2;     // 1600000
    const int* src = ei;
    const int* dst = ei + E;

    float *dA, *dB;
    cudaGetSymbolAddress((void**)&dA, g_bufA);
    cudaGetSymbolAddress((void**)&dB, g_bufB);

    const int TB = 256;
    const int NB = (n + SCAN_CHUNK - 1) / SCAN_CHUNK;
    const int GB = (n + 63) / 64;

    // fork: CSR chain on s2 overlapped with gemm128 on stream 0.
    // (stream/events not destroyed: referenced by the captured graph;
    //  kernel_launch runs only a handful of times)
    cudaStream_t s2;
    cudaEvent_t evA, evB;
    cudaStreamCreateWithFlags(&s2, cudaStreamNonBlocking);
    cudaEventCreateWithFlags(&evA, cudaEventDisableTiming);
    cudaEventCreateWithFlags(&evB, cudaEventDisableTiming);

    cudaEventRecord(evA, 0);
    cudaStreamWaitEvent(s2, evA, 0);

    // -- CSR chain (s2)
    k_zero_dc<<<(n + TB - 1) / TB, TB, 0, s2>>>(n);
    k_deg_hist<<<(E + TB - 1) / TB, TB, 0, s2>>>(dst, ew, E);
    k_scan1<<<NB, 1024, 0, s2>>>(n);
    k_scan2<<<1, 1024, 0, s2>>>(NB, n, E);
    k_scan3<<<(n + TB - 1) / TB, TB, 0, s2>>>(n);
    k_scatter<<<(E + TB - 1) / TB, TB, 0, s2>>>(src, dst, ew, E);
    cudaEventRecord(evB, s2);

    // -- stream 0: xw1 = x @ W1^T (independent of CSR chain)
    k_gemm<128><<<GB, TB>>>(x, W1, dA, n);

    // join, then serial tail
    cudaStreamWaitEvent(0, evB, 0);
    k_agg_relu<<<(n * 32 + TB - 1) / TB, TB>>>(dA, b1, dB, n);
    k_gemm<64><<<GB, TB>>>(dB, W2, dA, n);
    k_agg_head<<<(n * 32 + TB - 1) / TB, TB>>>(dA, b2, W3, b3, out, n);
}

// round 14
// speedup vs baseline: 1.1745x; 1.1322x over previous
#include <cuda_runtime.h>
#include <cuda_fp16.h>

// ---------------------------------------------------------------------------
// GCNRegression: 2x GCNConv(+relu) + linear head.
// N=100000, E=1.6M, F=128, H=64. edge_index arrives int32.
//
// R14 = R13 (best, 218.5us) + ONE change: transformed features (xw1, h1@W2)
// stored as fp16. All arithmetic stays fp32 (fp32 accumulate in GEMM and
// aggregation); conversion only at buffer write/read. Halves the dominant
// cost: per-edge 256B fp32 row gather -> 128B fp16 through L2.
//
//   s0: gemm128(f32->f16) -------------\
//   s2: zero hist scan1 scan2 scan3 scatter -> join ->
//        agg_relu(f16->f16) gemm64(f16->f16) agg_head(f16->f32)
// ---------------------------------------------------------------------------

#define NMAX 100000
#define EMAX 1600000
#define HID 64
#define SCAN_CHUNK 4096

__device__ __align__(16) float2 g_dc[NMAX];            // {deg_sum, count}
__device__ __align__(16) float  g_dis[NMAX];
__device__ __align__(16) int    g_rowptr[NMAX + 1];
__device__ __align__(16) int    g_pos[NMAX];
__device__ __align__(16) int    g_bsum[1024];
__device__ __align__(16) int    g_boff[1024];
__device__ __align__(16) float2 g_edge[EMAX];          // {src_as_float_bits, coef}
__device__ __align__(16) __half g_bufA[(size_t)NMAX * HID];
__device__ __align__(16) __half g_bufB[(size_t)NMAX * HID];

// ---- zero {deg, cnt} -------------------------------------------------------
__global__ void k_zero_dc(int n) {
    int i = blockIdx.x * blockDim.x + threadIdx.x;
    if (i < n) g_dc[i] = make_float2(0.f, 0.f);
}

// ---- weighted in-degree + histogram, one vector RED per edge ---------------
__global__ void k_deg_hist(const int* __restrict__ dst,
                           const float* __restrict__ ew, int E) {
    int e = blockIdx.x * blockDim.x + threadIdx.x;
    if (e < E) {
        int d = dst[e];
        float w = ew[e];
        asm volatile("red.global.add.v2.f32 [%0], {%1,%2};"
                     :: "l"(&g_dc[d]), "f"(w), "f"(1.0f) : "memory");
    }
}

// ---- scan phase 1 over counts (+ fused dis = rsqrt(1+deg)) -----------------
__global__ void k_scan1(int n) {
    __shared__ int ts[1024];
    int t = threadIdx.x, b = blockIdx.x;
    int base = b * SCAN_CHUNK + t * 4;
    int c[4];
#pragma unroll
    for (int r = 0; r < 4; r++) {
        if (base + r < n) {
            float2 dc = g_dc[base + r];
            c[r] = (int)dc.y;
            g_dis[base + r] = rsqrtf(1.0f + dc.x);
        } else c[r] = 0;
    }
    int s = c[0] + c[1] + c[2] + c[3];
    ts[t] = s;
    __syncthreads();
    for (int d = 1; d < 1024; d <<= 1) {
        int v = (t >= d) ? ts[t - d] : 0;
        __syncthreads();
        ts[t] += v;
        __syncthreads();
    }
    int excl = ts[t] - s;
    if (base + 0 < n) g_rowptr[base + 0] = excl;
    if (base + 1 < n) g_rowptr[base + 1] = excl + c[0];
    if (base + 2 < n) g_rowptr[base + 2] = excl + c[0] + c[1];
    if (base + 3 < n) g_rowptr[base + 3] = excl + c[0] + c[1] + c[2];
    if (t == 1023) g_bsum[b] = ts[1023];
}

// ---- scan phase 2: scan block sums (nb <= 1024) ----------------------------
__global__ void k_scan2(int nb, int n, int E) {
    __shared__ int ts[1024];
    int t = threadIdx.x;
    int v = (t < nb) ? g_bsum[t] : 0;
    ts[t] = v;
    __syncthreads();
    for (int d = 1; d < 1024; d <<= 1) {
        int u = (t >= d) ? ts[t - d] : 0;
        __syncthreads();
        ts[t] += u;
        __syncthreads();
    }
    if (t < nb) g_boff[t] = ts[t] - v;
    if (t == 0) g_rowptr[n] = E;
}

// ---- scan phase 3: add block offsets, init cursors -------------------------
__global__ void k_scan3(int n) {
    int i = blockIdx.x * blockDim.x + threadIdx.x;
    if (i < n) {
        int r = g_rowptr[i] + g_boff[i / SCAN_CHUNK];
        g_rowptr[i] = r;
        g_pos[i] = r;
    }
}

// ---- scatter edges into dst-sorted CSR order (packed meta) -----------------
__global__ void k_scatter(const int* __restrict__ src,
                          const int* __restrict__ dst,
                          const float* __restrict__ ew, int E) {
    int e = blockIdx.x * blockDim.x + threadIdx.x;
    if (e >= E) return;
    int s = src[e];
    int d = dst[e];
    int p = atomicAdd(&g_pos[d], 1);
    g_edge[p] = make_float2(__int_as_float(s), g_dis[s] * ew[e] * g_dis[d]);
}

// ---- packed helper: a += s * w (float4 lanewise) ---------------------------
__device__ __forceinline__ void fma4(float4& a, float s, const float4 w) {
    a.x = fmaf(s, w.x, a.x);
    a.y = fmaf(s, w.y, a.y);
    a.z = fmaf(s, w.z, a.z);
    a.w = fmaf(s, w.w, a.w);
}

__device__ __forceinline__ uint2 pack_half4(float4 a) {
    __half2 p0 = __floats2half2_rn(a.x, a.y);
    __half2 p1 = __floats2half2_rn(a.z, a.w);
    return make_uint2(*(unsigned*)&p0, *(unsigned*)&p1);
}

// ---- shared 4x4-register-tiled inner product -------------------------------
// 256 thr = 16x16 thread grid; block tile 64 rows x 64 cols; K chunked by 64.
// Staging of X differs per input dtype; W fp32; output fp16.

// variant A: X fp32 (layer 1, K=128)
__global__ __launch_bounds__(256) void k_gemm_f32in(
        const float* __restrict__ X, const float* __restrict__ W,
        __half* __restrict__ Y, int n) {
    const int K = 128;
    __shared__ float4 Xs4[64][16];
    __shared__ float  Wt[64][HID + 4];
    const int tid  = threadIdx.x;
    const int row0 = blockIdx.x * 64;
    const int r0   = (tid >> 4) * 4;
    const int c0   = (tid & 15) * 4;
    const float4* X4 = (const float4*)X;

    float4 acc0 = make_float4(0.f, 0.f, 0.f, 0.f);
    float4 acc1 = acc0, acc2 = acc0, acc3 = acc0;

    for (int kc = 0; kc < K; kc += 64) {
        if (kc) __syncthreads();
#pragma unroll
        for (int i = 0; i < 4; i++) {
            int idx = tid + i * 256;
            int r = idx >> 4, q = idx & 15;
            int row = row0 + r;
            Xs4[r][q] = (row < n) ? X4[(size_t)row * (K / 4) + (kc >> 2) + q]
                                  : make_float4(0.f, 0.f, 0.f, 0.f);
        }
#pragma unroll
        for (int i = 0; i < 16; i++) {
            int idx = tid + i * 256;
            int c = idx >> 6, k = idx & 63;
            Wt[k][c] = W[(size_t)c * K + kc + k];
        }
        __syncthreads();
#pragma unroll
        for (int t = 0; t < 16; t++) {
            float4 x0 = Xs4[r0 + 0][t];
            float4 x1 = Xs4[r0 + 1][t];
            float4 x2 = Xs4[r0 + 2][t];
            float4 x3 = Xs4[r0 + 3][t];
            float4 w0 = *(const float4*)&Wt[4 * t + 0][c0];
            float4 w1 = *(const float4*)&Wt[4 * t + 1][c0];
            float4 w2 = *(const float4*)&Wt[4 * t + 2][c0];
            float4 w3 = *(const float4*)&Wt[4 * t + 3][c0];
            fma4(acc0, x0.x, w0); fma4(acc0, x0.y, w1); fma4(acc0, x0.z, w2); fma4(acc0, x0.w, w3);
            fma4(acc1, x1.x, w0); fma4(acc1, x1.y, w1); fma4(acc1, x1.z, w2); fma4(acc1, x1.w, w3);
            fma4(acc2, x2.x, w0); fma4(acc2, x2.y, w1); fma4(acc2, x2.z, w2); fma4(acc2, x2.w, w3);
            fma4(acc3, x3.x, w0); fma4(acc3, x3.y, w1); fma4(acc3, x3.z, w2); fma4(acc3, x3.w, w3);
        }
    }
    const int tc = tid & 15;
#pragma unroll
    for (int i = 0; i < 4; i++) {
        int row = row0 + r0 + i;
        if (row < n) {
            float4 a = (i == 0) ? acc0 : (i == 1) ? acc1 : (i == 2) ? acc2 : acc3;
            ((uint2*)(Y + (size_t)row * HID))[tc] = pack_half4(a);
        }
    }
}

// variant B: X fp16 (layer 2, K=64)
__global__ __launch_bounds__(256) void k_gemm_f16in(
        const __half* __restrict__ X, const float* __restrict__ W,
        __half* __restrict__ Y, int n) {
    const int K = 64;
    __shared__ float4 Xs4[64][16];
    __shared__ float  Wt[64][HID + 4];
    const int tid  = threadIdx.x;
    const int row0 = blockIdx.x * 64;
    const int r0   = (tid >> 4) * 4;
    const int c0   = (tid & 15) * 4;
    const uint4* X8 = (const uint4*)X;      // 8 halves per uint4

    float4 acc0 = make_float4(0.f, 0.f, 0.f, 0.f);
    float4 acc1 = acc0, acc2 = acc0, acc3 = acc0;

    // single K-chunk (K == 64)
    // stage X: 64 rows x 8 uint4 (8 halves each) = 512 uint4s, 2 per thread
#pragma unroll
    for (int i = 0; i < 2; i++) {
        int idx = tid + i * 256;
        int r = idx >> 3, q = idx & 7;      // q-th group of 8 halves
        int row = row0 + r;
        uint4 u = (row < n) ? X8[(size_t)row * 8 + q]
                            : make_uint4(0u, 0u, 0u, 0u);
        float2 f0 = __half22float2(*(__half2*)&u.x);
        float2 f1 = __half22float2(*(__half2*)&u.y);
        float2 f2 = __half22float2(*(__half2*)&u.z);
        float2 f3 = __half22float2(*(__half2*)&u.w);
        Xs4[r][2 * q + 0] = make_float4(f0.x, f0.y, f1.x, f1.y);
        Xs4[r][2 * q + 1] = make_float4(f2.x, f2.y, f3.x, f3.y);
    }
#pragma unroll
    for (int i = 0; i < 16; i++) {
        int idx = tid + i * 256;
        int c = idx >> 6, k = idx & 63;
        Wt[k][c] = W[(size_t)c * K + k];
    }
    __syncthreads();
#pragma unroll
    for (int t = 0; t < 16; t++) {
        float4 x0 = Xs4[r0 + 0][t];
        float4 x1 = Xs4[r0 + 1][t];
        float4 x2 = Xs4[r0 + 2][t];
        float4 x3 = Xs4[r0 + 3][t];
        float4 w0 = *(const float4*)&Wt[4 * t + 0][c0];
        float4 w1 = *(const float4*)&Wt[4 * t + 1][c0];
        float4 w2 = *(const float4*)&Wt[4 * t + 2][c0];
        float4 w3 = *(const float4*)&Wt[4 * t + 3][c0];
        fma4(acc0, x0.x, w0); fma4(acc0, x0.y, w1); fma4(acc0, x0.z, w2); fma4(acc0, x0.w, w3);
        fma4(acc1, x1.x, w0); fma4(acc1, x1.y, w1); fma4(acc1, x1.z, w2); fma4(acc1, x1.w, w3);
        fma4(acc2, x2.x, w0); fma4(acc2, x2.y, w1); fma4(acc2, x2.z, w2); fma4(acc2, x2.w, w3);
        fma4(acc3, x3.x, w0); fma4(acc3, x3.y, w1); fma4(acc3, x3.z, w2); fma4(acc3, x3.w, w3);
    }
    const int tc = tid & 15;
#pragma unroll
    for (int i = 0; i < 4; i++) {
        int row = row0 + r0 + i;
        if (row < n) {
            float4 a = (i == 0) ? acc0 : (i == 1) ? acc1 : (i == 2) ? acc2 : acc3;
            ((uint2*)(Y + (size_t)row * HID))[tc] = pack_half4(a);
        }
    }
}

// ---- segmented-sum body over fp16 rows: acc (float2/lane) ------------------
__device__ __forceinline__ float2 ld_h2(const __half* __restrict__ xw,
                                        int s, int lane) {
    unsigned bits = __ldg((const unsigned*)(xw + (size_t)s * HID) + lane);
    return __half22float2(*(__half2*)&bits);
}

__device__ __forceinline__ void agg_body(const __half* __restrict__ xw,
                                         int node, int lane,
                                         float& ax, float& ay) {
    int j   = g_rowptr[node];
    int end = g_rowptr[node + 1];
    for (; j + 3 < end; j += 4) {
        float2 m0 = g_edge[j],     m1 = g_edge[j + 1];
        float2 m2 = g_edge[j + 2], m3 = g_edge[j + 3];
        float2 v0 = ld_h2(xw, __float_as_int(m0.x), lane);
        float2 v1 = ld_h2(xw, __float_as_int(m1.x), lane);
        float2 v2 = ld_h2(xw, __float_as_int(m2.x), lane);
        float2 v3 = ld_h2(xw, __float_as_int(m3.x), lane);
        ax = fmaf(m0.y, v0.x, ax); ay = fmaf(m0.y, v0.y, ay);
        ax = fmaf(m1.y, v1.x, ax); ay = fmaf(m1.y, v1.y, ay);
        ax = fmaf(m2.y, v2.x, ax); ay = fmaf(m2.y, v2.y, ay);
        ax = fmaf(m3.y, v3.x, ax); ay = fmaf(m3.y, v3.y, ay);
    }
    for (; j < end; j++) {
        float2 m = g_edge[j];
        float2 v = ld_h2(xw, __float_as_int(m.x), lane);
        ax = fmaf(m.y, v.x, ax); ay = fmaf(m.y, v.y, ay);
    }
}

// ---- layer aggregation + self-loop + bias + relu (1 warp/node) -------------
__global__ void k_agg_relu(const __half* __restrict__ xw,
                           const float* __restrict__ b,
                           __half* __restrict__ out, int n) {
    int node = (blockIdx.x * blockDim.x + threadIdx.x) >> 5;
    int lane = threadIdx.x & 31;
    if (node >= n) return;
    float ax = 0.f, ay = 0.f;
    agg_body(xw, node, lane, ax, ay);
    float ds = g_dis[node];
    float d2 = ds * ds;
    float2 xv = ld_h2(xw, node, lane);
    float2 bb = __ldg((const float2*)b + lane);
    float rx = fmaxf(fmaf(d2, xv.x, ax) + bb.x, 0.f);
    float ry = fmaxf(fmaf(d2, xv.y, ay) + bb.y, 0.f);
    __half2 p = __floats2half2_rn(rx, ry);
    ((unsigned*)(out + (size_t)node * HID))[lane] = *(unsigned*)&p;
}

// ---- final aggregation + relu + head dot W3 (1 warp/node) ------------------
__global__ void k_agg_head(const __half* __restrict__ xw,
                           const float* __restrict__ b2,
                           const float* __restrict__ W3,
                           const float* __restrict__ b3,
                           float* __restrict__ out, int n) {
    int node = (blockIdx.x * blockDim.x + threadIdx.x) >> 5;
    int lane = threadIdx.x & 31;
    if (node >= n) return;
    float ax = 0.f, ay = 0.f;
    agg_body(xw, node, lane, ax, ay);
    float ds = g_dis[node];
    float d2 = ds * ds;
    float2 xv = ld_h2(xw, node, lane);
    float2 bb = __ldg((const float2*)b2 + lane);
    float h0 = fmaxf(fmaf(d2, xv.x, ax) + bb.x, 0.f);
    float h1 = fmaxf(fmaf(d2, xv.y, ay) + bb.y, 0.f);
    float2 w = __ldg((const float2*)W3 + lane);
    float sum = fmaf(h0, w.x, h1 * w.y);
#pragma unroll
    for (int off = 16; off; off >>= 1)
        sum += __shfl_xor_sync(0xffffffffu, sum, off);
    if (lane == 0) out[node] = sum + b3[0];
}

extern "C" void kernel_launch(void* const* d_in, const int* in_sizes, int n_in,
                              void* d_out, int out_size) {
    const float* x   = (const float*)d_in[0];
    const int*   ei  = (const int*)d_in[1];       // int32 (JAX x64 disabled)
    const float* ew  = (const float*)d_in[2];
    // d_in[3] = batch (unused)
    const float* W1  = (const float*)d_in[4];
    const float* b1  = (const float*)d_in[5];
    const float* W2  = (const float*)d_in[6];
    const float* b2  = (const float*)d_in[7];
    const float* W3  = (const float*)d_in[8];
    const float* b3  = (const float*)d_in[9];
    float*       out = (float*)d_out;

    const int n = in_sizes[0] / 128;   // 100000
    const int E = in_sizes[1] / 2;     // 1600000
    const int* src = ei;
    const int* dst = ei + E;

    __half *dA, *dB;
    cudaGetSymbolAddress((void**)&dA, g_bufA);
    cudaGetSymbolAddress((void**)&dB, g_bufB);

    const int TB = 256;
    const int NB = (n + SCAN_CHUNK - 1) / SCAN_CHUNK;
    const int GB = (n + 63) / 64;

    // fork: CSR chain on s2 overlapped with gemm128 on stream 0.
    cudaStream_t s2;
    cudaEvent_t evA, evB;
    cudaStreamCreateWithFlags(&s2, cudaStreamNonBlocking);
    cudaEventCreateWithFlags(&evA, cudaEventDisableTiming);
    cudaEventCreateWithFlags(&evB, cudaEventDisableTiming);

    cudaEventRecord(evA, 0);
    cudaStreamWaitEvent(s2, evA, 0);

    // -- CSR chain (s2)
    k_zero_dc<<<(n + TB - 1) / TB, TB, 0, s2>>>(n);
    k_deg_hist<<<(E + TB - 1) / TB, TB, 0, s2>>>(dst, ew, E);
    k_scan1<<<NB, 1024, 0, s2>>>(n);
    k_scan2<<<1, 1024, 0, s2>>>(NB, n, E);
    k_scan3<<<(n + TB - 1) / TB, TB, 0, s2>>>(n);
    k_scatter<<<(E + TB - 1) / TB, TB, 0, s2>>>(src, dst, ew, E);
    cudaEventRecord(evB, s2);

    // -- stream 0: xw1 = x @ W1^T (fp16 out)
    k_gemm_f32in<<<GB, TB>>>(x, W1, dA, n);

    // join, then serial tail
    cudaStreamWaitEvent(0, evB, 0);
    k_agg_relu<<<(n * 32 + TB - 1) / TB, TB>>>(dA, b1, dB, n);
    k_gemm_f16in<<<GB, TB>>>(dB, W2, dA, n);
    k_agg_head<<<(n * 32 + TB - 1) / TB, TB>>>(dA, b2, W3, b3, out, n);
}

// round 15
// speedup vs baseline: 1.5158x; 1.2907x over previous
#include <cuda_runtime.h>
#include <cuda_fp16.h>

// ---------------------------------------------------------------------------
// GCNRegression: 2x GCNConv(+relu) + linear head.
// N=100000, E=1.6M, F=128, H=64. edge_index arrives int32.
//
// R15 = R14 (best, 193.0us) + ONE change: both GEMMs rewritten as fp16
// tensor-core kernels (mma.sync.m16n8k16, fp32 accumulate, fp16 out).
// SIMT GEMMs were at the fp32 FFMA floor (57+29us); HMMA makes them
// memory-bound (~15+5us). Inputs rounded to fp16 (x, W) -> expected
// rel_err ~1e-4, still 10x under the 1e-3 gate.
// ---------------------------------------------------------------------------

#define NMAX 100000
#define EMAX 1600000
#define HID 64
#define SCAN_CHUNK 4096

__device__ __align__(16) float2 g_dc[NMAX];            // {deg_sum, count}
__device__ __align__(16) float  g_dis[NMAX];
__device__ __align__(16) int    g_rowptr[NMAX + 1];
__device__ __align__(16) int    g_pos[NMAX];
__device__ __align__(16) int    g_bsum[1024];
__device__ __align__(16) int    g_boff[1024];
__device__ __align__(16) float2 g_edge[EMAX];          // {src_as_float_bits, coef}
__device__ __align__(16) __half g_bufA[(size_t)NMAX * HID];
__device__ __align__(16) __half g_bufB[(size_t)NMAX * HID];

// ---- zero {deg, cnt} -------------------------------------------------------
__global__ void k_zero_dc(int n) {
    int i = blockIdx.x * blockDim.x + threadIdx.x;
    if (i < n) g_dc[i] = make_float2(0.f, 0.f);
}

// ---- weighted in-degree + histogram, one vector RED per edge ---------------
__global__ void k_deg_hist(const int* __restrict__ dst,
                           const float* __restrict__ ew, int E) {
    int e = blockIdx.x * blockDim.x + threadIdx.x;
    if (e < E) {
        int d = dst[e];
        float w = ew[e];
        asm volatile("red.global.add.v2.f32 [%0], {%1,%2};"
                     :: "l"(&g_dc[d]), "f"(w), "f"(1.0f) : "memory");
    }
}

// ---- scan phase 1 over counts (+ fused dis = rsqrt(1+deg)) -----------------
__global__ void k_scan1(int n) {
    __shared__ int ts[1024];
    int t = threadIdx.x, b = blockIdx.x;
    int base = b * SCAN_CHUNK + t * 4;
    int c[4];
#pragma unroll
    for (int r = 0; r < 4; r++) {
        if (base + r < n) {
            float2 dc = g_dc[base + r];
            c[r] = (int)dc.y;
            g_dis[base + r] = rsqrtf(1.0f + dc.x);
        } else c[r] = 0;
    }
    int s = c[0] + c[1] + c[2] + c[3];
    ts[t] = s;
    __syncthreads();
    for (int d = 1; d < 1024; d <<= 1) {
        int v = (t >= d) ? ts[t - d] : 0;
        __syncthreads();
        ts[t] += v;
        __syncthreads();
    }
    int excl = ts[t] - s;
    if (base + 0 < n) g_rowptr[base + 0] = excl;
    if (base + 1 < n) g_rowptr[base + 1] = excl + c[0];
    if (base + 2 < n) g_rowptr[base + 2] = excl + c[0] + c[1];
    if (base + 3 < n) g_rowptr[base + 3] = excl + c[0] + c[1] + c[2];
    if (t == 1023) g_bsum[b] = ts[1023];
}

// ---- scan phase 2: scan block sums (nb <= 1024) ----------------------------
__global__ void k_scan2(int nb, int n, int E) {
    __shared__ int ts[1024];
    int t = threadIdx.x;
    int v = (t < nb) ? g_bsum[t] : 0;
    ts[t] = v;
    __syncthreads();
    for (int d = 1; d < 1024; d <<= 1) {
        int u = (t >= d) ? ts[t - d] : 0;
        __syncthreads();
        ts[t] += u;
        __syncthreads();
    }
    if (t < nb) g_boff[t] = ts[t] - v;
    if (t == 0) g_rowptr[n] = E;
}

// ---- scan phase 3: add block offsets, init cursors -------------------------
__global__ void k_scan3(int n) {
    int i = blockIdx.x * blockDim.x + threadIdx.x;
    if (i < n) {
        int r = g_rowptr[i] + g_boff[i / SCAN_CHUNK];
        g_rowptr[i] = r;
        g_pos[i] = r;
    }
}

// ---- scatter edges into dst-sorted CSR order (packed meta) -----------------
__global__ void k_scatter(const int* __restrict__ src,
                          const int* __restrict__ dst,
                          const float* __restrict__ ew, int E) {
    int e = blockIdx.x * blockDim.x + threadIdx.x;
    if (e >= E) return;
    int s = src[e];
    int d = dst[e];
    int p = atomicAdd(&g_pos[d], 1);
    g_edge[p] = make_float2(__int_as_float(s), g_dis[s] * ew[e] * g_dis[d]);
}

// ---- tensor-core GEMM: Y[n,64] = X[n,K] @ W[64,K]^T  (fp16 in, f32 acc) ----
// 256 thr = 8 warps; block tile 128 rows x 64 cols; warp = 16 rows x 64 cols
// (8 n-tiles of m16n8k16). K chunked by 64 halves. Smem rows padded to 72
// halves (144B pitch) -> fragment LDS.32s (8 rows apart) are conflict-free.
// Fragment thread mapping per PTX m16n8k16: g=lane>>2, tq=lane&3.
#define XPITCH 72

template <int K, bool F16IN>
__global__ __launch_bounds__(256) void k_gemm_tc(
        const void* __restrict__ Xv, const float* __restrict__ W,
        __half* __restrict__ Y, int n) {
    __shared__ __half Xs[128][XPITCH];
    __shared__ __half Wt[64][XPITCH];

    const int tid  = threadIdx.x;
    const int warp = tid >> 5;
    const int lane = tid & 31;
    const int g    = lane >> 2;
    const int tq   = lane & 3;
    const int row0 = blockIdx.x * 128;
    const int rA   = warp * 16 + g;          // local A-row for a0/a2 (a1/a3: +8)

    float d0[8], d1[8], d2[8], d3[8];
#pragma unroll
    for (int t = 0; t < 8; t++) { d0[t] = d1[t] = d2[t] = d3[t] = 0.f; }

    for (int kc = 0; kc < K; kc += 64) {
        if (kc) __syncthreads();
        // ---- stage X chunk (128 rows x 64 halves)
        if (F16IN) {
            const uint4* X8 = (const uint4*)Xv;   // 8 halves each
#pragma unroll
            for (int i = 0; i < 4; i++) {
                int idx = tid + i * 256;          // 1024 = 128*8
                int r = idx >> 3, q = idx & 7;
                int row = row0 + r;
                uint4 u = (row < n) ? X8[(size_t)row * (K / 8) + (kc >> 3) + q]
                                    : make_uint4(0u, 0u, 0u, 0u);
                *(uint4*)&Xs[r][q * 8] = u;
            }
        } else {
            const float4* X4 = (const float4*)Xv;
#pragma unroll
            for (int i = 0; i < 8; i++) {
                int idx = tid + i * 256;          // 2048 = 128*16
                int r = idx >> 4, q = idx & 15;
                int row = row0 + r;
                float4 a = (row < n) ? X4[(size_t)row * (K / 4) + (kc >> 2) + q]
                                     : make_float4(0.f, 0.f, 0.f, 0.f);
                __half2 p0 = __floats2half2_rn(a.x, a.y);
                __half2 p1 = __floats2half2_rn(a.z, a.w);
                *(uint2*)&Xs[r][q * 4] = make_uint2(*(unsigned*)&p0, *(unsigned*)&p1);
            }
        }
        // ---- stage W chunk transposed to fp16: Wt[c][k] = W[c*K + kc + k]
#pragma unroll
        for (int i = 0; i < 16; i++) {
            int idx = tid + i * 256;              // 4096 = 64*64
            int c = idx >> 6, k = idx & 63;
            Wt[c][k] = __float2half(W[(size_t)c * K + kc + k]);
        }
        __syncthreads();

        // ---- 4 k16-steps per chunk
#pragma unroll
        for (int ks = 0; ks < 64; ks += 16) {
            unsigned a0 = *(const unsigned*)&Xs[rA][ks + tq * 2];
            unsigned a1 = *(const unsigned*)&Xs[rA + 8][ks + tq * 2];
            unsigned a2 = *(const unsigned*)&Xs[rA][ks + tq * 2 + 8];
            unsigned a3 = *(const unsigned*)&Xs[rA + 8][ks + tq * 2 + 8];
#pragma unroll
            for (int nt = 0; nt < 8; nt++) {
                unsigned b0 = *(const unsigned*)&Wt[nt * 8 + g][ks + tq * 2];
                unsigned b1 = *(const unsigned*)&Wt[nt * 8 + g][ks + tq * 2 + 8];
                asm volatile(
                    "mma.sync.aligned.m16n8k16.row.col.f32.f16.f16.f32 "
                    "{%0,%1,%2,%3}, {%4,%5,%6,%7}, {%8,%9}, {%0,%1,%2,%3};"
                    : "+f"(d0[nt]), "+f"(d1[nt]), "+f"(d2[nt]), "+f"(d3[nt])
                    : "r"(a0), "r"(a1), "r"(a2), "r"(a3), "r"(b0), "r"(b1));
            }
        }
    }

    // ---- store: D[g][tq*2..+1] and D[g+8][tq*2..+1] per n-tile, fp16 packed
    int rowA = row0 + warp * 16 + g;
    int rowB = rowA + 8;
#pragma unroll
    for (int nt = 0; nt < 8; nt++) {
        int col = nt * 8 + tq * 2;
        if (rowA < n) {
            __half2 p = __floats2half2_rn(d0[nt], d1[nt]);
            *(unsigned*)&Y[(size_t)rowA * HID + col] = *(unsigned*)&p;
        }
        if (rowB < n) {
            __half2 p = __floats2half2_rn(d2[nt], d3[nt]);
            *(unsigned*)&Y[(size_t)rowB * HID + col] = *(unsigned*)&p;
        }
    }
}

// ---- segmented-sum body over fp16 rows: acc (float2/lane) ------------------
__device__ __forceinline__ float2 ld_h2(const __half* __restrict__ xw,
                                        int s, int lane) {
    unsigned bits = __ldg((const unsigned*)(xw + (size_t)s * HID) + lane);
    return __half22float2(*(__half2*)&bits);
}

__device__ __forceinline__ void agg_body(const __half* __restrict__ xw,
                                         int node, int lane,
                                         float& ax, float& ay) {
    int j   = g_rowptr[node];
    int end = g_rowptr[node + 1];
    for (; j + 3 < end; j += 4) {
        float2 m0 = g_edge[j],     m1 = g_edge[j + 1];
        float2 m2 = g_edge[j + 2], m3 = g_edge[j + 3];
        float2 v0 = ld_h2(xw, __float_as_int(m0.x), lane);
        float2 v1 = ld_h2(xw, __float_as_int(m1.x), lane);
        float2 v2 = ld_h2(xw, __float_as_int(m2.x), lane);
        float2 v3 = ld_h2(xw, __float_as_int(m3.x), lane);
        ax = fmaf(m0.y, v0.x, ax); ay = fmaf(m0.y, v0.y, ay);
        ax = fmaf(m1.y, v1.x, ax); ay = fmaf(m1.y, v1.y, ay);
        ax = fmaf(m2.y, v2.x, ax); ay = fmaf(m2.y, v2.y, ay);
        ax = fmaf(m3.y, v3.x, ax); ay = fmaf(m3.y, v3.y, ay);
    }
    for (; j < end; j++) {
        float2 m = g_edge[j];
        float2 v = ld_h2(xw, __float_as_int(m.x), lane);
        ax = fmaf(m.y, v.x, ax); ay = fmaf(m.y, v.y, ay);
    }
}

// ---- layer aggregation + self-loop + bias + relu (1 warp/node) -------------
__global__ void k_agg_relu(const __half* __restrict__ xw,
                           const float* __restrict__ b,
                           __half* __restrict__ out, int n) {
    int node = (blockIdx.x * blockDim.x + threadIdx.x) >> 5;
    int lane = threadIdx.x & 31;
    if (node >= n) return;
    float ax = 0.f, ay = 0.f;
    agg_body(xw, node, lane, ax, ay);
    float ds = g_dis[node];
    float d2 = ds * ds;
    float2 xv = ld_h2(xw, node, lane);
    float2 bb = __ldg((const float2*)b + lane);
    float rx = fmaxf(fmaf(d2, xv.x, ax) + bb.x, 0.f);
    float ry = fmaxf(fmaf(d2, xv.y, ay) + bb.y, 0.f);
    __half2 p = __floats2half2_rn(rx, ry);
    ((unsigned*)(out + (size_t)node * HID))[lane] = *(unsigned*)&p;
}

// ---- final aggregation + relu + head dot W3 (1 warp/node) ------------------
__global__ void k_agg_head(const __half* __restrict__ xw,
                           const float* __restrict__ b2,
                           const float* __restrict__ W3,
                           const float* __restrict__ b3,
                           float* __restrict__ out, int n) {
    int node = (blockIdx.x * blockDim.x + threadIdx.x) >> 5;
    int lane = threadIdx.x & 31;
    if (node >= n) return;
    float ax = 0.f, ay = 0.f;
    agg_body(xw, node, lane, ax, ay);
    float ds = g_dis[node];
    float d2 = ds * ds;
    float2 xv = ld_h2(xw, node, lane);
    float2 bb = __ldg((const float2*)b2 + lane);
    float h0 = fmaxf(fmaf(d2, xv.x, ax) + bb.x, 0.f);
    float h1 = fmaxf(fmaf(d2, xv.y, ay) + bb.y, 0.f);
    float2 w = __ldg((const float2*)W3 + lane);
    float sum = fmaf(h0, w.x, h1 * w.y);
#pragma unroll
    for (int off = 16; off; off >>= 1)
        sum += __shfl_xor_sync(0xffffffffu, sum, off);
    if (lane == 0) out[node] = sum + b3[0];
}

extern "C" void kernel_launch(void* const* d_in, const int* in_sizes, int n_in,
                              void* d_out, int out_size) {
    const float* x   = (const float*)d_in[0];
    const int*   ei  = (const int*)d_in[1];       // int32 (JAX x64 disabled)
    const float* ew  = (const float*)d_in[2];
    // d_in[3] = batch (unused)
    const float* W1  = (const float*)d_in[4];
    const float* b1  = (const float*)d_in[5];
    const float* W2  = (const float*)d_in[6];
    const float* b2  = (const float*)d_in[7];
    const float* W3  = (const float*)d_in[8];
    const float* b3  = (const float*)d_in[9];
    float*       out = (float*)d_out;

    const int n = in_sizes[0] / 128;   // 100000
    const int E = in_sizes[1] / 2;     // 1600000
    const int* src = ei;
    const int* dst = ei + E;

    __half *dA, *dB;
    cudaGetSymbolAddress((void**)&dA, g_bufA);
    cudaGetSymbolAddress((void**)&dB, g_bufB);

    const int TB = 256;
    const int NB = (n + SCAN_CHUNK - 1) / SCAN_CHUNK;
    const int GB = (n + 127) / 128;               // 128-row gemm blocks

    // fork: CSR chain on s2, gemm128 on stream 0 (overlap mostly pipelining,
    // kept from R13/R14 — harmless and slightly positive)
    cudaStream_t s2;
    cudaEvent_t evA, evB;
    cudaStreamCreateWithFlags(&s2, cudaStreamNonBlocking);
    cudaEventCreateWithFlags(&evA, cudaEventDisableTiming);
    cudaEventCreateWithFlags(&evB, cudaEventDisableTiming);

    cudaEventRecord(evA, 0);
    cudaStreamWaitEvent(s2, evA, 0);

    // -- CSR chain (s2)
    k_zero_dc<<<(n + TB - 1) / TB, TB, 0, s2>>>(n);
    k_deg_hist<<<(E + TB - 1) / TB, TB, 0, s2>>>(dst, ew, E);
    k_scan1<<<NB, 1024, 0, s2>>>(n);
    k_scan2<<<1, 1024, 0, s2>>>(NB, n, E);
    k_scan3<<<(n + TB - 1) / TB, TB, 0, s2>>>(n);
    k_scatter<<<(E + TB - 1) / TB, TB, 0, s2>>>(src, dst, ew, E);
    cudaEventRecord(evB, s2);

    // -- stream 0: xw1 = x @ W1^T (tensor cores, fp16 out)
    k_gemm_tc<128, false><<<GB, TB>>>(x, W1, dA, n);

    // join, then serial tail
    cudaStreamWaitEvent(0, evB, 0);
    k_agg_relu<<<(n * 32 + TB - 1) / TB, TB>>>(dA, b1, dB, n);
    k_gemm_tc<64, true><<<GB, TB>>>(dB, W2, dA, n);
    k_agg_head<<<(n * 32 + TB - 1) / TB, TB>>>(dA, b2, W3, b3, out, n);
}